// round 1
// baseline (speedup 1.0000x reference)
#include <cuda_runtime.h>
#include <math.h>

#define N_NODES 50000
#define N_EDGES 800000
#define D 128

// ---------------- static scratch (no allocations allowed) ----------------
__device__ float g_h [N_NODES * D];
__device__ float g_hn[N_NODES * D];
__device__ int   g_deg[N_NODES];
__device__ float g_invdeg[N_NODES];
__device__ int   g_rowptr[N_NODES + 1];
__device__ int   g_pos[N_NODES];
__device__ int   g_col[N_EDGES];

// ---------------- CSR build ----------------
__global__ void zero_deg_kernel() {
    int i = blockIdx.x * blockDim.x + threadIdx.x;
    if (i < N_NODES) g_deg[i] = 0;
}

__global__ void count_kernel(const int* __restrict__ dst) {
    int e = blockIdx.x * blockDim.x + threadIdx.x;
    if (e < N_EDGES) atomicAdd(&g_deg[dst[e]], 1);
}

// single-block scan over 50000 degrees -> rowptr / pos / invdeg
__global__ void scan_kernel() {
    __shared__ int part[1024];
    const int CH = (N_NODES + 1023) / 1024;  // 49
    int t = threadIdx.x;
    int start = t * CH;
    int end = start + CH; if (end > N_NODES) end = N_NODES;
    int s = 0;
    for (int i = start; i < end; i++) s += g_deg[i];
    part[t] = s;
    __syncthreads();
    // inclusive Hillis-Steele
    for (int off = 1; off < 1024; off <<= 1) {
        int v = 0;
        if (t >= off) v = part[t - off];
        __syncthreads();
        if (t >= off) part[t] += v;
        __syncthreads();
    }
    int run = (t == 0) ? 0 : part[t - 1];
    for (int i = start; i < end; i++) {
        g_rowptr[i] = run;
        g_pos[i]    = run;
        int d = g_deg[i];
        g_invdeg[i] = 1.0f / (float)(d > 1 ? d : 1);
        run += d;
    }
    if (t == 1023) g_rowptr[N_NODES] = part[1023];
}

__global__ void fill_kernel(const int* __restrict__ src, const int* __restrict__ dst) {
    int e = blockIdx.x * blockDim.x + threadIdx.x;
    if (e < N_EDGES) {
        int d = dst[e];
        int idx = atomicAdd(&g_pos[d], 1);
        g_col[idx] = src[e];
    }
}

// ---------------- mean aggregation: one warp per node ----------------
__global__ void agg_kernel(const float* __restrict__ h, float* __restrict__ hn) {
    int wid  = (blockIdx.x * blockDim.x + threadIdx.x) >> 5;
    int lane = threadIdx.x & 31;
    if (wid >= N_NODES) return;
    int beg = g_rowptr[wid], end = g_rowptr[wid + 1];
    float4 acc = make_float4(0.f, 0.f, 0.f, 0.f);
    for (int e = beg; e < end; e++) {
        int s = g_col[e];
        float4 v = *(const float4*)(h + (size_t)s * D + lane * 4);
        acc.x += v.x; acc.y += v.y; acc.z += v.z; acc.w += v.w;
    }
    float inv = g_invdeg[wid];
    acc.x *= inv; acc.y *= inv; acc.z *= inv; acc.w *= inv;
    *(float4*)(hn + (size_t)wid * D + lane * 4) = acc;
}

// ---------------- GEMM: out = act( (BETA? Cin:0) + A@W + bias ) ----------------
// Block: 256 threads, 64 rows x 128 cols per block.
// W (128x128) fully in smem; A tile (64x129 padded) in smem.
// Thread (r = tid&63, cg = tid>>6) computes row r, cols [cg*32, cg*32+32).
// ACT: 0 = none, 1 = tanh, 2 = silu
template <int BETA, int ACT>
__global__ void gemm128(const float* __restrict__ A, const float* __restrict__ W,
                        const float* __restrict__ bias,
                        const float* __restrict__ Cin, float* __restrict__ Cout,
                        int n) {
    extern __shared__ float sm[];
    float* Ws = sm;            // 128*128 = 16384 floats
    float* As = sm + 16384;    // 64*129  = 8256 floats
    int tid = threadIdx.x;

    // load W (4096 float4)
    const float4* Wg  = (const float4*)W;
    float4*       Ws4 = (float4*)Ws;
    #pragma unroll
    for (int i = tid; i < 4096; i += 256) Ws4[i] = Wg[i];

    // load A tile (64 rows x 32 float4), padded stride 129
    int row0 = blockIdx.x * 64;
    #pragma unroll
    for (int i = tid; i < 2048; i += 256) {
        int r = i >> 5;
        int c = (i & 31) * 4;
        int gr = row0 + r;
        float4 v = make_float4(0.f, 0.f, 0.f, 0.f);
        if (gr < n) v = *(const float4*)(A + (size_t)gr * D + c);
        float* p = As + r * 129 + c;
        p[0] = v.x; p[1] = v.y; p[2] = v.z; p[3] = v.w;
    }
    __syncthreads();

    int r  = tid & 63;
    int cg = tid >> 6;
    float acc[32];
    #pragma unroll
    for (int j = 0; j < 32; j++) acc[j] = 0.f;

    const float* arow = As + r * 129;
    #pragma unroll 2
    for (int k = 0; k < 128; k++) {
        float a = arow[k];
        const float4* w4 = (const float4*)(Ws + k * 128 + cg * 32);
        #pragma unroll
        for (int j = 0; j < 8; j++) {
            float4 w = w4[j];
            acc[4 * j + 0] += a * w.x;
            acc[4 * j + 1] += a * w.y;
            acc[4 * j + 2] += a * w.z;
            acc[4 * j + 3] += a * w.w;
        }
    }

    int grow = row0 + r;
    if (grow < n) {
        size_t base = (size_t)grow * D + cg * 32;
        #pragma unroll
        for (int j = 0; j < 8; j++) {
            float4 v;
            float* pv = &v.x;
            #pragma unroll
            for (int q = 0; q < 4; q++) {
                float x = acc[4 * j + q];
                if (bias) x += bias[cg * 32 + 4 * j + q];
                if (BETA) x += Cin[base + 4 * j + q];
                if (ACT == 1) x = tanhf(x);
                else if (ACT == 2) x = x / (1.f + expf(-x));
                pv[q] = x;
            }
            *(float4*)(Cout + base + 4 * j) = v;
        }
    }
}

// ---------------- launch ----------------
extern "C" void kernel_launch(void* const* d_in, const int* in_sizes, int n_in,
                              void* d_out, int out_size) {
    const float* h_in   = (const float*)d_in[0];
    const int*   src    = (const int*)  d_in[1];
    const int*   dst    = (const int*)  d_in[2];
    const float* W_in1  = (const float*)d_in[3];
    const float* b_in1  = (const float*)d_in[4];
    const float* W_in2  = (const float*)d_in[5];
    const float* b_in2  = (const float*)d_in[6];
    const float* W_self = (const float*)d_in[7];
    const float* b_self = (const float*)d_in[8];
    const float* W_neigh= (const float*)d_in[9];
    float* out = (float*)d_out;

    const int SMEM = (16384 + 64 * 129) * 4;  // 98560 bytes
    static bool attr_done = false;
    // idempotent; re-calling is harmless and keeps kernel_launch deterministic
    cudaFuncSetAttribute(gemm128<0, 0>, cudaFuncAttributeMaxDynamicSharedMemorySize, SMEM);
    cudaFuncSetAttribute(gemm128<0, 1>, cudaFuncAttributeMaxDynamicSharedMemorySize, SMEM);
    cudaFuncSetAttribute(gemm128<1, 1>, cudaFuncAttributeMaxDynamicSharedMemorySize, SMEM);
    cudaFuncSetAttribute(gemm128<1, 2>, cudaFuncAttributeMaxDynamicSharedMemorySize, SMEM);
    (void)attr_done;

    float* gh  = nullptr;
    float* ghn = nullptr;
    cudaGetSymbolAddress((void**)&gh,  g_h);
    cudaGetSymbolAddress((void**)&ghn, g_hn);

    const int GEMM_GRID = (N_NODES + 63) / 64;  // 782
    const int EB = (N_EDGES + 255) / 256;
    const int NB = (N_NODES + 255) / 256;
    const int AGG_GRID = (N_NODES * 32 + 255) / 256;  // warp per node

    // ---- CSR build (graph is identical for all 3 layers) ----
    zero_deg_kernel<<<NB, 256>>>();
    count_kernel<<<EB, 256>>>(dst);
    scan_kernel<<<1, 1024>>>();
    fill_kernel<<<EB, 256>>>(src, dst);

    // ---- fc_in: h = tanh(h@W1 + b1) @ W2 + b2 ----
    gemm128<0, 1><<<GEMM_GRID, 256, SMEM>>>(h_in, W_in1, b_in1, nullptr, gh, N_NODES);
    gemm128<0, 0><<<GEMM_GRID, 256, SMEM>>>(gh,   W_in2, b_in2, nullptr, gh, N_NODES);

    // ---- 3 SAGE layers ----
    for (int i = 0; i < 3; i++) {
        const float* Ws = W_self  + (size_t)i * D * D;
        const float* bs = b_self  + (size_t)i * D;
        const float* Wn = W_neigh + (size_t)i * D * D;

        agg_kernel<<<AGG_GRID, 256>>>(gh, ghn);
        // pass 1: gh = gh@Ws + bs   (in-place safe: block reads own rows first)
        gemm128<0, 0><<<GEMM_GRID, 256, SMEM>>>(gh, Ws, bs, nullptr, gh, N_NODES);
        // pass 2: accumulate neighbor term + activation
        if (i < 2) {
            gemm128<1, 2><<<GEMM_GRID, 256, SMEM>>>(ghn, Wn, nullptr, gh, gh, N_NODES);   // silu
        } else {
            gemm128<1, 1><<<GEMM_GRID, 256, SMEM>>>(ghn, Wn, nullptr, gh, out, N_NODES);  // tanh -> out
        }
    }
}

// round 3
// speedup vs baseline: 1.8386x; 1.8386x over previous
#include <cuda_runtime.h>
#include <cuda_bf16.h>
#include <cstdint>
#include <math.h>

#define N_NODES 50000
#define N_EDGES 800000
#define D 128

// ---------------- static scratch ----------------
__device__ float g_h [N_NODES * D];
__device__ float g_hn[N_NODES * D];
__device__ int   g_deg[N_NODES];
__device__ float g_invdeg[N_NODES];
__device__ int   g_rowptr[N_NODES + 1];
__device__ int   g_pos[N_NODES];
__device__ int   g_col[N_EDGES];

// ---------------- helpers ----------------
__device__ __forceinline__ uint32_t smem_u32(const void* p) {
    uint32_t a;
    asm("{ .reg .u64 t; cvta.to.shared.u64 t, %1; cvt.u32.u64 %0, t; }" : "=r"(a) : "l"(p));
    return a;
}
__device__ __forceinline__ void ldsm_x4(uint32_t* r, uint32_t addr) {
    asm volatile("ldmatrix.sync.aligned.m8n8.x4.shared.b16 {%0,%1,%2,%3}, [%4];"
                 : "=r"(r[0]), "=r"(r[1]), "=r"(r[2]), "=r"(r[3]) : "r"(addr));
}
__device__ __forceinline__ void ldsm_x2t(uint32_t* r, uint32_t addr) {
    asm volatile("ldmatrix.sync.aligned.m8n8.x2.trans.shared.b16 {%0,%1}, [%2];"
                 : "=r"(r[0]), "=r"(r[1]) : "r"(addr));
}
__device__ __forceinline__ void mma_bf16(float* c, const uint32_t* a, const uint32_t* b) {
    asm volatile(
        "mma.sync.aligned.m16n8k16.row.col.f32.bf16.bf16.f32 "
        "{%0,%1,%2,%3}, {%4,%5,%6,%7}, {%8,%9}, {%0,%1,%2,%3};"
        : "+f"(c[0]), "+f"(c[1]), "+f"(c[2]), "+f"(c[3])
        : "r"(a[0]), "r"(a[1]), "r"(a[2]), "r"(a[3]), "r"(b[0]), "r"(b[1]));
}
__device__ __forceinline__ void split_pack4(float4 v, uint2& hi, uint2& lo) {
    __nv_bfloat16 h0 = __float2bfloat16(v.x);
    __nv_bfloat16 h1 = __float2bfloat16(v.y);
    __nv_bfloat16 h2 = __float2bfloat16(v.z);
    __nv_bfloat16 h3 = __float2bfloat16(v.w);
    __nv_bfloat16 l0 = __float2bfloat16(v.x - __bfloat162float(h0));
    __nv_bfloat16 l1 = __float2bfloat16(v.y - __bfloat162float(h1));
    __nv_bfloat16 l2 = __float2bfloat16(v.z - __bfloat162float(h2));
    __nv_bfloat16 l3 = __float2bfloat16(v.w - __bfloat162float(h3));
    hi.x = (uint32_t)__bfloat16_as_ushort(h0) | ((uint32_t)__bfloat16_as_ushort(h1) << 16);
    hi.y = (uint32_t)__bfloat16_as_ushort(h2) | ((uint32_t)__bfloat16_as_ushort(h3) << 16);
    lo.x = (uint32_t)__bfloat16_as_ushort(l0) | ((uint32_t)__bfloat16_as_ushort(l1) << 16);
    lo.y = (uint32_t)__bfloat16_as_ushort(l2) | ((uint32_t)__bfloat16_as_ushort(l3) << 16);
}

// ---------------- CSR build ----------------
__global__ void zero_deg_kernel() {
    int i = blockIdx.x * blockDim.x + threadIdx.x;
    if (i < N_NODES) g_deg[i] = 0;
}
__global__ void count_kernel(const int* __restrict__ dst) {
    int e = blockIdx.x * blockDim.x + threadIdx.x;
    if (e < N_EDGES) atomicAdd(&g_deg[dst[e]], 1);
}
__global__ void scan_kernel() {
    __shared__ int part[1024];
    const int CH = (N_NODES + 1023) / 1024;
    int t = threadIdx.x;
    int start = t * CH;
    int end = start + CH; if (end > N_NODES) end = N_NODES;
    int s = 0;
    for (int i = start; i < end; i++) s += g_deg[i];
    part[t] = s;
    __syncthreads();
    for (int off = 1; off < 1024; off <<= 1) {
        int v = 0;
        if (t >= off) v = part[t - off];
        __syncthreads();
        if (t >= off) part[t] += v;
        __syncthreads();
    }
    int run = (t == 0) ? 0 : part[t - 1];
    for (int i = start; i < end; i++) {
        g_rowptr[i] = run;
        g_pos[i]    = run;
        int d = g_deg[i];
        g_invdeg[i] = 1.0f / (float)(d > 1 ? d : 1);
        run += d;
    }
    if (t == 1023) g_rowptr[N_NODES] = part[1023];
}
__global__ void fill_kernel(const int* __restrict__ src, const int* __restrict__ dst) {
    int e = blockIdx.x * blockDim.x + threadIdx.x;
    if (e < N_EDGES) {
        int d = dst[e];
        int idx = atomicAdd(&g_pos[d], 1);
        g_col[idx] = src[e];
    }
}

// ---------------- mean aggregation: one warp per node ----------------
__global__ void agg_kernel(const float* __restrict__ h, float* __restrict__ hn) {
    int wid  = (blockIdx.x * blockDim.x + threadIdx.x) >> 5;
    int lane = threadIdx.x & 31;
    if (wid >= N_NODES) return;
    int beg = g_rowptr[wid], end = g_rowptr[wid + 1];
    float4 acc = make_float4(0.f, 0.f, 0.f, 0.f);
    for (int e = beg; e < end; e++) {
        int s = g_col[e];
        float4 v = *(const float4*)(h + (size_t)s * D + lane * 4);
        acc.x += v.x; acc.y += v.y; acc.z += v.z; acc.w += v.w;
    }
    float inv = g_invdeg[wid];
    acc.x *= inv; acc.y *= inv; acc.z *= inv; acc.w *= inv;
    *(float4*)(hn + (size_t)wid * D + lane * 4) = acc;
}

// ---------------- split-bf16 mma.sync GEMM ----------------
// Cout = act( (BETA?Cin:0) + A@W + bias );  M tile 128, N=128, K=128.
// A,W fp32 -> hi/lo bf16; acc fp32 = Ahi*Whi + Ahi*Wlo + Alo*Whi.
// SMEM rows padded to 136 bf16 (272 B) -> conflict-free ldmatrix.
// Warp (wid): wm = (wid&1)*64 rows, wn = (wid>>1)*32 cols.
#define PITCH 272
#define TILE_BYTES (128 * PITCH)   // 34816

template <int BETA, int ACT>
__global__ void __launch_bounds__(256, 1)
mma_gemm(const float* __restrict__ A, const float* __restrict__ W,
         const float* __restrict__ bias, const float* __restrict__ Cin,
         float* __restrict__ Cout, int n) {
    extern __shared__ char smem[];
    char* As_hi = smem;
    char* As_lo = smem + TILE_BYTES;
    char* Bs_hi = smem + 2 * TILE_BYTES;
    char* Bs_lo = smem + 3 * TILE_BYTES;

    int tid = threadIdx.x, lane = tid & 31, wid = tid >> 5;
    int row0 = blockIdx.x * 128;

    // load + split A tile (guarded)
    #pragma unroll 4
    for (int i = tid; i < 4096; i += 256) {
        int r = i >> 5, c = (i & 31) << 2;
        int gr = row0 + r;
        float4 v = make_float4(0.f, 0.f, 0.f, 0.f);
        if (gr < n) v = *(const float4*)(A + (size_t)gr * D + c);
        uint2 h, l;
        split_pack4(v, h, l);
        *(uint2*)(As_hi + r * PITCH + c * 2) = h;
        *(uint2*)(As_lo + r * PITCH + c * 2) = l;
    }
    // load + split W tile ([k][n] row-major, used via ldmatrix.trans)
    #pragma unroll 4
    for (int i = tid; i < 4096; i += 256) {
        int r = i >> 5, c = (i & 31) << 2;
        float4 v = *(const float4*)(W + (size_t)r * D + c);
        uint2 h, l;
        split_pack4(v, h, l);
        *(uint2*)(Bs_hi + r * PITCH + c * 2) = h;
        *(uint2*)(Bs_lo + r * PITCH + c * 2) = l;
    }
    __syncthreads();

    int wm = (wid & 1) * 64;
    int wn = (wid >> 1) * 32;

    float acc[4][4][4];
    #pragma unroll
    for (int mt = 0; mt < 4; mt++)
        #pragma unroll
        for (int nt = 0; nt < 4; nt++)
            #pragma unroll
            for (int q = 0; q < 4; q++) acc[mt][nt][q] = 0.f;

    // ldmatrix lane addressing
    uint32_t a_hi0 = smem_u32(As_hi) + (uint32_t)(wm + (lane & 15)) * PITCH + (lane >> 4) * 16;
    uint32_t a_lo0 = a_hi0 + TILE_BYTES;                       // As_lo at +TILE_BYTES
    uint32_t b_hi0 = smem_u32(Bs_hi) + (uint32_t)(lane & 15) * PITCH + wn * 2;
    uint32_t b_lo0 = b_hi0 + TILE_BYTES;

    #pragma unroll
    for (int k = 0; k < 8; k++) {
        uint32_t ah[4][4], al[4][4], bh[4][2], bl[4][2];
        #pragma unroll
        for (int nt = 0; nt < 4; nt++) {
            ldsm_x2t(bh[nt], b_hi0 + (uint32_t)k * (16 * PITCH) + nt * 16);
            ldsm_x2t(bl[nt], b_lo0 + (uint32_t)k * (16 * PITCH) + nt * 16);
        }
        #pragma unroll
        for (int mt = 0; mt < 4; mt++) {
            ldsm_x4(ah[mt], a_hi0 + (uint32_t)mt * (16 * PITCH) + k * 32);
            ldsm_x4(al[mt], a_lo0 + (uint32_t)mt * (16 * PITCH) + k * 32);
        }
        #pragma unroll
        for (int mt = 0; mt < 4; mt++)
            #pragma unroll
            for (int nt = 0; nt < 4; nt++) {
                mma_bf16(acc[mt][nt], ah[mt], bh[nt]);
                mma_bf16(acc[mt][nt], ah[mt], bl[nt]);
                mma_bf16(acc[mt][nt], al[mt], bh[nt]);
            }
    }

    // epilogue
    int mrow = lane >> 2;
    int mcol = (lane & 3) * 2;
    #pragma unroll
    for (int mt = 0; mt < 4; mt++) {
        #pragma unroll
        for (int half = 0; half < 2; half++) {
            int gr = row0 + wm + mt * 16 + mrow + half * 8;
            if (gr < n) {
                size_t rb = (size_t)gr * D;
                #pragma unroll
                for (int nt = 0; nt < 4; nt++) {
                    int col = wn + nt * 8 + mcol;
                    float x0 = acc[mt][nt][half * 2 + 0];
                    float x1 = acc[mt][nt][half * 2 + 1];
                    if (bias) { x0 += bias[col]; x1 += bias[col + 1]; }
                    if (BETA) {
                        float2 cv = *(const float2*)(Cin + rb + col);
                        x0 += cv.x; x1 += cv.y;
                    }
                    if (ACT == 1)      { x0 = tanhf(x0); x1 = tanhf(x1); }
                    else if (ACT == 2) { x0 = x0 / (1.f + expf(-x0)); x1 = x1 / (1.f + expf(-x1)); }
                    *(float2*)(Cout + rb + col) = make_float2(x0, x1);
                }
            }
        }
    }
}

// ---------------- launch ----------------
extern "C" void kernel_launch(void* const* d_in, const int* in_sizes, int n_in,
                              void* d_out, int out_size) {
    const float* h_in    = (const float*)d_in[0];
    const int*   src     = (const int*)  d_in[1];
    const int*   dst     = (const int*)  d_in[2];
    const float* W_in1   = (const float*)d_in[3];
    const float* b_in1   = (const float*)d_in[4];
    const float* W_in2   = (const float*)d_in[5];
    const float* b_in2   = (const float*)d_in[6];
    const float* W_self  = (const float*)d_in[7];
    const float* b_self  = (const float*)d_in[8];
    const float* W_neigh = (const float*)d_in[9];
    float* out = (float*)d_out;

    const int SMEM = 4 * TILE_BYTES;  // 139264 B
    cudaFuncSetAttribute(mma_gemm<0, 0>, cudaFuncAttributeMaxDynamicSharedMemorySize, SMEM);
    cudaFuncSetAttribute(mma_gemm<0, 1>, cudaFuncAttributeMaxDynamicSharedMemorySize, SMEM);
    cudaFuncSetAttribute(mma_gemm<1, 1>, cudaFuncAttributeMaxDynamicSharedMemorySize, SMEM);
    cudaFuncSetAttribute(mma_gemm<1, 2>, cudaFuncAttributeMaxDynamicSharedMemorySize, SMEM);

    float* gh  = nullptr;
    float* ghn = nullptr;
    cudaGetSymbolAddress((void**)&gh,  g_h);
    cudaGetSymbolAddress((void**)&ghn, g_hn);

    const int GEMM_GRID = (N_NODES + 127) / 128;  // 391
    const int EB = (N_EDGES + 255) / 256;
    const int NB = (N_NODES + 255) / 256;
    const int AGG_GRID = (N_NODES * 32 + 255) / 256;

    // ---- CSR build ----
    zero_deg_kernel<<<NB, 256>>>();
    count_kernel<<<EB, 256>>>(dst);
    scan_kernel<<<1, 1024>>>();
    fill_kernel<<<EB, 256>>>(src, dst);

    // ---- fc_in: h = tanh(h@W1 + b1) @ W2 + b2 ----
    mma_gemm<0, 1><<<GEMM_GRID, 256, SMEM>>>(h_in, W_in1, b_in1, nullptr, gh, N_NODES);
    mma_gemm<0, 0><<<GEMM_GRID, 256, SMEM>>>(gh,   W_in2, b_in2, nullptr, gh, N_NODES);

    // ---- 3 SAGE layers ----
    for (int i = 0; i < 3; i++) {
        const float* Ws = W_self  + (size_t)i * D * D;
        const float* bs = b_self  + (size_t)i * D;
        const float* Wn = W_neigh + (size_t)i * D * D;

        agg_kernel<<<AGG_GRID, 256>>>(gh, ghn);
        mma_gemm<0, 0><<<GEMM_GRID, 256, SMEM>>>(gh, Ws, bs, nullptr, gh, N_NODES);
        if (i < 2) {
            mma_gemm<1, 2><<<GEMM_GRID, 256, SMEM>>>(ghn, Wn, nullptr, gh, gh, N_NODES);   // +silu
        } else {
            mma_gemm<1, 1><<<GEMM_GRID, 256, SMEM>>>(ghn, Wn, nullptr, gh, out, N_NODES);  // +tanh
        }
    }
}

// round 6
// speedup vs baseline: 2.2274x; 1.2115x over previous
#include <cuda_runtime.h>
#include <cuda_bf16.h>
#include <cstdint>
#include <math.h>

#define N_NODES 50000
#define N_EDGES 800000
#define D 128

// ---------------- static scratch ----------------
__device__ float g_h [N_NODES * D];   // ping
__device__ float g_h2[N_NODES * D];   // pong
__device__ float g_hn[N_NODES * D];   // aggregated neighbors
__device__ int   g_deg[N_NODES];
__device__ float g_invdeg[N_NODES];
__device__ int   g_rowptr[N_NODES + 1];
__device__ int   g_pos[N_NODES];
__device__ int   g_col[N_EDGES];
__device__ __align__(16) __nv_bfloat16 g_Whi[8 * 16384];
__device__ __align__(16) __nv_bfloat16 g_Wlo[8 * 16384];

// ---------------- helpers ----------------
__device__ __forceinline__ uint32_t smem_u32(const void* p) {
    uint32_t a;
    asm("{ .reg .u64 t; cvta.to.shared.u64 t, %1; cvt.u32.u64 %0, t; }" : "=r"(a) : "l"(p));
    return a;
}
__device__ __forceinline__ void ldsm_x4(uint32_t* r, uint32_t addr) {
    asm volatile("ldmatrix.sync.aligned.m8n8.x4.shared.b16 {%0,%1,%2,%3}, [%4];"
                 : "=r"(r[0]), "=r"(r[1]), "=r"(r[2]), "=r"(r[3]) : "r"(addr));
}
__device__ __forceinline__ void ldsm_x2t(uint32_t* r, uint32_t addr) {
    asm volatile("ldmatrix.sync.aligned.m8n8.x2.trans.shared.b16 {%0,%1}, [%2];"
                 : "=r"(r[0]), "=r"(r[1]) : "r"(addr));
}
__device__ __forceinline__ void mma_bf16(float* c, const uint32_t* a, const uint32_t* b) {
    asm volatile(
        "mma.sync.aligned.m16n8k16.row.col.f32.bf16.bf16.f32 "
        "{%0,%1,%2,%3}, {%4,%5,%6,%7}, {%8,%9}, {%0,%1,%2,%3};"
        : "+f"(c[0]), "+f"(c[1]), "+f"(c[2]), "+f"(c[3])
        : "r"(a[0]), "r"(a[1]), "r"(a[2]), "r"(a[3]), "r"(b[0]), "r"(b[1]));
}
__device__ __forceinline__ void split_pack4(float4 v, uint2& hi, uint2& lo) {
    __nv_bfloat16 h0 = __float2bfloat16(v.x);
    __nv_bfloat16 h1 = __float2bfloat16(v.y);
    __nv_bfloat16 h2 = __float2bfloat16(v.z);
    __nv_bfloat16 h3 = __float2bfloat16(v.w);
    __nv_bfloat16 l0 = __float2bfloat16(v.x - __bfloat162float(h0));
    __nv_bfloat16 l1 = __float2bfloat16(v.y - __bfloat162float(h1));
    __nv_bfloat16 l2 = __float2bfloat16(v.z - __bfloat162float(h2));
    __nv_bfloat16 l3 = __float2bfloat16(v.w - __bfloat162float(h3));
    hi.x = (uint32_t)__bfloat16_as_ushort(h0) | ((uint32_t)__bfloat16_as_ushort(h1) << 16);
    hi.y = (uint32_t)__bfloat16_as_ushort(h2) | ((uint32_t)__bfloat16_as_ushort(h3) << 16);
    lo.x = (uint32_t)__bfloat16_as_ushort(l0) | ((uint32_t)__bfloat16_as_ushort(l1) << 16);
    lo.y = (uint32_t)__bfloat16_as_ushort(l2) | ((uint32_t)__bfloat16_as_ushort(l3) << 16);
}

// ---------------- CSR build ----------------
__global__ void zero_deg_kernel() {
    int i = blockIdx.x * blockDim.x + threadIdx.x;
    if (i < N_NODES) g_deg[i] = 0;
}
__global__ void count_kernel(const int* __restrict__ dst) {
    int e = blockIdx.x * blockDim.x + threadIdx.x;
    if (e < N_EDGES) atomicAdd(&g_deg[dst[e]], 1);
}
__global__ void scan_kernel() {
    __shared__ int part[1024];
    const int CH = (N_NODES + 1023) / 1024;
    int t = threadIdx.x;
    int start = t * CH;
    int end = start + CH; if (end > N_NODES) end = N_NODES;
    int s = 0;
    for (int i = start; i < end; i++) s += g_deg[i];
    part[t] = s;
    __syncthreads();
    for (int off = 1; off < 1024; off <<= 1) {
        int v = 0;
        if (t >= off) v = part[t - off];
        __syncthreads();
        if (t >= off) part[t] += v;
        __syncthreads();
    }
    int run = (t == 0) ? 0 : part[t - 1];
    for (int i = start; i < end; i++) {
        g_rowptr[i] = run;
        g_pos[i]    = run;
        int d = g_deg[i];
        g_invdeg[i] = 1.0f / (float)(d > 1 ? d : 1);
        run += d;
    }
    if (t == 1023) g_rowptr[N_NODES] = part[1023];
}
__global__ void fill_kernel(const int* __restrict__ src, const int* __restrict__ dst) {
    int e = blockIdx.x * blockDim.x + threadIdx.x;
    if (e < N_EDGES) {
        int d = dst[e];
        int idx = atomicAdd(&g_pos[d], 1);
        g_col[idx] = src[e];
    }
}

// ---------------- W precompute: fp32 -> hi/lo bf16, 8 slots ----------------
// slot 0: W_in1, 1: W_in2, 2..4: W_self[i], 5..7: W_neigh[i]
__global__ void wprep_kernel(const float* __restrict__ W1, const float* __restrict__ W2,
                             const float* __restrict__ Wself, const float* __restrict__ Wneigh) {
    int idx = blockIdx.x * blockDim.x + threadIdx.x;
    if (idx >= 8 * 16384) return;
    int slot = idx >> 14, off = idx & 16383;
    const float* src;
    if (slot == 0)      src = W1;
    else if (slot == 1) src = W2;
    else if (slot < 5)  src = Wself + (size_t)(slot - 2) * 16384;
    else                src = Wneigh + (size_t)(slot - 5) * 16384;
    float v = src[off];
    __nv_bfloat16 h = __float2bfloat16(v);
    g_Whi[idx] = h;
    g_Wlo[idx] = __float2bfloat16(v - __bfloat162float(h));
}

// ---------------- mean aggregation: one warp per node (proven R1/R3 path) ----------------
__global__ void agg_kernel(const float* __restrict__ h, float* __restrict__ hn) {
    int wid  = (blockIdx.x * blockDim.x + threadIdx.x) >> 5;
    int lane = threadIdx.x & 31;
    if (wid >= N_NODES) return;
    int beg = g_rowptr[wid], end = g_rowptr[wid + 1];
    float4 acc = make_float4(0.f, 0.f, 0.f, 0.f);
    int e = beg;
    for (; e + 4 <= end; e += 4) {
        int s0 = g_col[e], s1 = g_col[e + 1], s2 = g_col[e + 2], s3 = g_col[e + 3];
        float4 v0 = *(const float4*)(h + (size_t)s0 * D + lane * 4);
        float4 v1 = *(const float4*)(h + (size_t)s1 * D + lane * 4);
        float4 v2 = *(const float4*)(h + (size_t)s2 * D + lane * 4);
        float4 v3 = *(const float4*)(h + (size_t)s3 * D + lane * 4);
        acc.x += v0.x + v1.x + v2.x + v3.x;
        acc.y += v0.y + v1.y + v2.y + v3.y;
        acc.z += v0.z + v1.z + v2.z + v3.z;
        acc.w += v0.w + v1.w + v2.w + v3.w;
    }
    for (; e < end; e++) {
        int s = g_col[e];
        float4 v = *(const float4*)(h + (size_t)s * D + lane * 4);
        acc.x += v.x; acc.y += v.y; acc.z += v.z; acc.w += v.w;
    }
    float inv = g_invdeg[wid];
    acc.x *= inv; acc.y *= inv; acc.z *= inv; acc.w *= inv;
    *(float4*)(hn + (size_t)wid * D + lane * 4) = acc;
}

// ---------------- shared GEMM building blocks ----------------
#define PITCH 272
#define TILE_BYTES (128 * PITCH)   // 34816
#define SMEM_TOTAL_BYTES (4 * TILE_BYTES)
// layout: As_hi | As_lo | Bs_hi | Bs_lo

__device__ __forceinline__ void load_split_A(const float* __restrict__ src, int row0, int n,
                                             char* As_hi, char* As_lo, int tid) {
    #pragma unroll 4
    for (int i = tid; i < 4096; i += 256) {
        int r = i >> 5, c = (i & 31) << 2;
        int gr = row0 + r;
        float4 v = make_float4(0.f, 0.f, 0.f, 0.f);
        if (gr < n) v = *(const float4*)(src + (size_t)gr * D + c);
        uint2 h, l;
        split_pack4(v, h, l);
        *(uint2*)(As_hi + r * PITCH + c * 2) = h;
        *(uint2*)(As_lo + r * PITCH + c * 2) = l;
    }
}

__device__ __forceinline__ void load_B_prepped(int slot, char* Bs_hi, char* Bs_lo, int tid) {
    const __nv_bfloat16* whi = g_Whi + (size_t)slot * 16384;
    const __nv_bfloat16* wlo = g_Wlo + (size_t)slot * 16384;
    #pragma unroll 4
    for (int i = tid; i < 2048; i += 256) {
        int r = i >> 4, c = (i & 15) << 3;
        *(uint4*)(Bs_hi + r * PITCH + c * 2) = *(const uint4*)(whi + r * D + c);
        *(uint4*)(Bs_lo + r * PITCH + c * 2) = *(const uint4*)(wlo + r * D + c);
    }
}

// main MMA loop: acc += A @ B (3-term split). lo tiles at +TILE_BYTES.
__device__ __forceinline__ void mma_mainloop(float acc[4][4][4], uint32_t a_hi0, uint32_t b_hi0) {
    #pragma unroll
    for (int k = 0; k < 8; k++) {
        uint32_t ah[4][4], al[4][4], bh[4][2], bl[4][2];
        #pragma unroll
        for (int nt = 0; nt < 4; nt++) {
            ldsm_x2t(bh[nt], b_hi0 + (uint32_t)k * (16 * PITCH) + nt * 16);
            ldsm_x2t(bl[nt], b_hi0 + TILE_BYTES + (uint32_t)k * (16 * PITCH) + nt * 16);
        }
        #pragma unroll
        for (int mt = 0; mt < 4; mt++) {
            ldsm_x4(ah[mt], a_hi0 + (uint32_t)mt * (16 * PITCH) + k * 32);
            ldsm_x4(al[mt], a_hi0 + TILE_BYTES + (uint32_t)mt * (16 * PITCH) + k * 32);
        }
        #pragma unroll
        for (int mt = 0; mt < 4; mt++)
            #pragma unroll
            for (int nt = 0; nt < 4; nt++) {
                mma_bf16(acc[mt][nt], ah[mt], bh[nt]);
                mma_bf16(acc[mt][nt], ah[mt], bl[nt]);
                mma_bf16(acc[mt][nt], al[mt], bh[nt]);
            }
    }
}

__device__ __forceinline__ void zero_acc(float acc[4][4][4]) {
    #pragma unroll
    for (int mt = 0; mt < 4; mt++)
        #pragma unroll
        for (int nt = 0; nt < 4; nt++)
            #pragma unroll
            for (int q = 0; q < 4; q++) acc[mt][nt][q] = 0.f;
}

__device__ __forceinline__ void epilogue(float acc[4][4][4], const float* __restrict__ bias,
                                         float* __restrict__ Cout, int row0, int n,
                                         int wm, int wn, int lane, int ACT) {
    int mrow = lane >> 2;
    int mcol = (lane & 3) * 2;
    #pragma unroll
    for (int mt = 0; mt < 4; mt++)
        #pragma unroll
        for (int half = 0; half < 2; half++) {
            int gr = row0 + wm + mt * 16 + mrow + half * 8;
            if (gr < n) {
                size_t rb = (size_t)gr * D;
                #pragma unroll
                for (int nt = 0; nt < 4; nt++) {
                    int col = wn + nt * 8 + mcol;
                    float x0 = acc[mt][nt][half * 2 + 0];
                    float x1 = acc[mt][nt][half * 2 + 1];
                    if (bias) { x0 += bias[col]; x1 += bias[col + 1]; }
                    if (ACT == 1)      { x0 = tanhf(x0); x1 = tanhf(x1); }
                    else if (ACT == 2) { x0 = x0 / (1.f + expf(-x0)); x1 = x1 / (1.f + expf(-x1)); }
                    *(float2*)(Cout + rb + col) = make_float2(x0, x1);
                }
            }
        }
}

// ---------------- single GEMM: Cout = act(A@W[slot] + bias) ----------------
template <int ACT>
__global__ void __launch_bounds__(256, 1)
gemm_kernel(const float* __restrict__ A, int slot, const float* __restrict__ bias,
            float* __restrict__ Cout, int n) {
    extern __shared__ char smem[];
    char* As_hi = smem;
    char* As_lo = smem + TILE_BYTES;
    char* Bs_hi = smem + 2 * TILE_BYTES;
    char* Bs_lo = smem + 3 * TILE_BYTES;

    int tid = threadIdx.x, lane = tid & 31, wid = tid >> 5;
    int row0 = blockIdx.x * 128;
    int wm = (wid & 1) * 64;
    int wn = (wid >> 1) * 32;

    load_split_A(A, row0, n, As_hi, As_lo, tid);
    load_B_prepped(slot, Bs_hi, Bs_lo, tid);
    __syncthreads();

    uint32_t a_hi0 = smem_u32(As_hi) + (uint32_t)(wm + (lane & 15)) * PITCH + (lane >> 4) * 16;
    uint32_t b_hi0 = smem_u32(Bs_hi) + (uint32_t)(lane & 15) * PITCH + wn * 2;

    float acc[4][4][4];
    zero_acc(acc);
    mma_mainloop(acc, a_hi0, b_hi0);
    epilogue(acc, bias, Cout, row0, n, wm, wn, lane, ACT);
}

// ---------------- fused SAGE layer: out = act(in@Ws + bias + hn@Wn) ----------------
template <int ACT>
__global__ void __launch_bounds__(256, 1)
layer_kernel(const float* __restrict__ in, const float* __restrict__ hn,
             int slot_self, int slot_neigh,
             const float* __restrict__ bias, float* __restrict__ Cout, int n) {
    extern __shared__ char smem[];
    char* As_hi = smem;
    char* As_lo = smem + TILE_BYTES;
    char* Bs_hi = smem + 2 * TILE_BYTES;
    char* Bs_lo = smem + 3 * TILE_BYTES;

    int tid = threadIdx.x, lane = tid & 31, wid = tid >> 5;
    int row0 = blockIdx.x * 128;
    int wm = (wid & 1) * 64;
    int wn = (wid >> 1) * 32;

    uint32_t a_hi0 = smem_u32(As_hi) + (uint32_t)(wm + (lane & 15)) * PITCH + (lane >> 4) * 16;
    uint32_t b_hi0 = smem_u32(Bs_hi) + (uint32_t)(lane & 15) * PITCH + wn * 2;

    float acc[4][4][4];
    zero_acc(acc);

    // phase 1: self term
    load_split_A(in, row0, n, As_hi, As_lo, tid);
    load_B_prepped(slot_self, Bs_hi, Bs_lo, tid);
    __syncthreads();
    mma_mainloop(acc, a_hi0, b_hi0);
    __syncthreads();

    // phase 2: neighbor term
    load_split_A(hn, row0, n, As_hi, As_lo, tid);
    load_B_prepped(slot_neigh, Bs_hi, Bs_lo, tid);
    __syncthreads();
    mma_mainloop(acc, a_hi0, b_hi0);

    epilogue(acc, bias, Cout, row0, n, wm, wn, lane, ACT);
}

// ---------------- launch ----------------
extern "C" void kernel_launch(void* const* d_in, const int* in_sizes, int n_in,
                              void* d_out, int out_size) {
    const float* h_in    = (const float*)d_in[0];
    const int*   src     = (const int*)  d_in[1];
    const int*   dst     = (const int*)  d_in[2];
    const float* W_in1   = (const float*)d_in[3];
    const float* b_in1   = (const float*)d_in[4];
    const float* W_in2   = (const float*)d_in[5];
    const float* b_in2   = (const float*)d_in[6];
    const float* W_self  = (const float*)d_in[7];
    const float* b_self  = (const float*)d_in[8];
    const float* W_neigh = (const float*)d_in[9];
    float* out = (float*)d_out;

    cudaFuncSetAttribute(gemm_kernel<0>,  cudaFuncAttributeMaxDynamicSharedMemorySize, SMEM_TOTAL_BYTES);
    cudaFuncSetAttribute(gemm_kernel<1>,  cudaFuncAttributeMaxDynamicSharedMemorySize, SMEM_TOTAL_BYTES);
    cudaFuncSetAttribute(layer_kernel<1>, cudaFuncAttributeMaxDynamicSharedMemorySize, SMEM_TOTAL_BYTES);
    cudaFuncSetAttribute(layer_kernel<2>, cudaFuncAttributeMaxDynamicSharedMemorySize, SMEM_TOTAL_BYTES);

    float* buf0 = nullptr;
    float* buf1 = nullptr;
    float* hn   = nullptr;
    cudaGetSymbolAddress((void**)&buf0, g_h);
    cudaGetSymbolAddress((void**)&buf1, g_h2);
    cudaGetSymbolAddress((void**)&hn,   g_hn);

    const int GEMM_GRID = (N_NODES + 127) / 128;  // 391
    const int EB = (N_EDGES + 255) / 256;
    const int NB = (N_NODES + 255) / 256;
    const int AGG_GRID = (N_NODES * 32 + 255) / 256;

    // ---- CSR build + W precompute ----
    zero_deg_kernel<<<NB, 256>>>();
    count_kernel<<<EB, 256>>>(dst);
    scan_kernel<<<1, 1024>>>();
    fill_kernel<<<EB, 256>>>(src, dst);
    wprep_kernel<<<512, 256>>>(W_in1, W_in2, W_self, W_neigh);

    // ---- fc_in: buf0 = tanh(h@W1+b1)@W2 + b2 ----
    gemm_kernel<1><<<GEMM_GRID, 256, SMEM_TOTAL_BYTES>>>(h_in, 0, b_in1, buf1, N_NODES);
    gemm_kernel<0><<<GEMM_GRID, 256, SMEM_TOTAL_BYTES>>>(buf1, 1, b_in2, buf0, N_NODES);

    // ---- 3 SAGE layers: agg then fused dual-GEMM ----
    agg_kernel<<<AGG_GRID, 256>>>(buf0, hn);
    layer_kernel<2><<<GEMM_GRID, 256, SMEM_TOTAL_BYTES>>>(buf0, hn, 2, 5, b_self + 0 * D, buf1, N_NODES);

    agg_kernel<<<AGG_GRID, 256>>>(buf1, hn);
    layer_kernel<2><<<GEMM_GRID, 256, SMEM_TOTAL_BYTES>>>(buf1, hn, 3, 6, b_self + 1 * D, buf0, N_NODES);

    agg_kernel<<<AGG_GRID, 256>>>(buf0, hn);
    layer_kernel<1><<<GEMM_GRID, 256, SMEM_TOTAL_BYTES>>>(buf0, hn, 4, 7, b_self + 2 * D, out, N_NODES);
}